// round 13
// baseline (speedup 1.0000x reference)
#include <cuda_runtime.h>
#include <cuda.h>
#include <cuda_bf16.h>
#include <math.h>
#include <cstdint>

#define Bb 64
#define Ff 256
#define Tt 1024
#define Hh 1024
#define Oo 512
#define RNCTA 128         // 2 b-halves x 64 n-blocks (co-resident single wave)
#define NCOL 16           // hidden columns per recurrence CTA
#define WSTR 2064         // Wh smem row stride bytes (2048 + 16 pad)

// SMEM layout
#define OFF_WHI 0
#define OFF_WLO 33024                     // 16 * WSTR
#define MB_BASE 66048                     // 2 mbarriers @ +0, +8
#define OFF_S   66560                     // 1024-aligned; hi 64KB + lo 64KB
#define S_MAT_BYTES 65536                 // 32 b-rows x 1024 k x 2B per matrix
#define HALF_TX 65536                     // per-half tx bytes (hi 32KB + lo 32KB)
#define OFF_RED (OFF_S + 2 * S_MAT_BYTES) // 197632
#define SMEM_TOTAL (OFF_RED + 12 * 32 * 16)   // +6KB reduction = 203776

typedef unsigned long long ull;

// ---------------- device globals (no allocation allowed) ----------------
__device__ float g_xT[(size_t)Tt * Bb * Ff];          // x as (T,B,F)
__device__ float g_U [(size_t)Tt * Hh * Bb];          // U then fp32 states, [t][h][b]
__device__ __nv_bfloat16 g_WhiT[(size_t)Hh * Hh];     // Wh^T hi  [h][k]
__device__ __nv_bfloat16 g_WloT[(size_t)Hh * Hh];     // Wh^T lo  [h][k]
__device__ __nv_bfloat16 g_Sh[2][(size_t)Bb * Hh];    // state hi, [buf][b][k]
__device__ __nv_bfloat16 g_Sl[2][(size_t)Bb * Hh];    // state lo
__device__ unsigned int g_cnt;                        // legacy grid barrier (end only)
__device__ unsigned int g_sense;
__device__ unsigned int g_flag[RNCTA];                // per-CTA step-completion flags

// ---------------- helpers ----------------
__device__ __forceinline__ uint32_t smem_u32(const void* p) {
    uint32_t a;
    asm("{ .reg .u64 t; cvta.to.shared.u64 t, %1; cvt.u32.u64 %0, t; }" : "=r"(a) : "l"(p));
    return a;
}
__device__ __forceinline__ float ftanh(float x) {
    float xc = fminf(fmaxf(x, -15.0f), 15.0f);
    float e  = __expf(2.0f * xc);
    return __fdividef(e - 1.0f, e + 1.0f);
}
__device__ __forceinline__ ull pk2(float lo, float hi) {
    ull r; asm("mov.b64 %0, {%1, %2};" : "=l"(r) : "f"(lo), "f"(hi)); return r;
}
__device__ __forceinline__ ull ffma2(ull a, ull b, ull c) {
    ull d; asm("fma.rn.f32x2 %0, %1, %2, %3;" : "=l"(d) : "l"(a), "l"(b), "l"(c)); return d;
}
__device__ __forceinline__ float2 upk2(ull v) {
    float2 f; asm("mov.b64 {%0, %1}, %2;" : "=f"(f.x), "=f"(f.y) : "l"(v)); return f;
}

// mma.sync m16n8k16 bf16 -> fp32 (base ISA on compute_103)
__device__ __forceinline__ void mma16816(float* d, const uint32_t* a, uint32_t b0, uint32_t b1) {
    asm volatile("mma.sync.aligned.m16n8k16.row.col.f32.bf16.bf16.f32 "
        "{%0,%1,%2,%3}, {%4,%5,%6,%7}, {%8,%9}, {%0,%1,%2,%3};"
        : "+f"(d[0]), "+f"(d[1]), "+f"(d[2]), "+f"(d[3])
        : "r"(a[0]), "r"(a[1]), "r"(a[2]), "r"(a[3]), "r"(b0), "r"(b1));
}
__device__ __forceinline__ void ldsm4(uint32_t* r, uint32_t addr) {
    asm volatile("ldmatrix.sync.aligned.m8n8.x4.shared.b16 {%0,%1,%2,%3}, [%4];"
        : "=r"(r[0]), "=r"(r[1]), "=r"(r[2]), "=r"(r[3]) : "r"(addr));
}

// ---------------- TMA / mbarrier (base-ISA) ----------------
#define MBARRIER_INIT(mbar, count) \
    asm volatile("mbarrier.init.shared.b64 [%0], %1;" \
        :: "r"((uint32_t)(mbar)), "r"((uint32_t)(count)) : "memory")
#define MBARRIER_EXPECT_TX(mbar, tx) \
    asm volatile("mbarrier.arrive.expect_tx.shared.b64 _, [%0], %1;" \
        :: "r"((uint32_t)(mbar)), "r"((uint32_t)(tx)) : "memory")
#define MBARRIER_WAIT_PARITY(mbar, parity) do {                                    \
    uint32_t _m = (uint32_t)(mbar), _p = (uint32_t)(parity), _done;                \
    asm volatile("{\n\t.reg .pred p;\n\t"                                          \
        "mbarrier.try_wait.parity.acquire.cta.shared::cta.b64 p, [%1], %2;\n\t"    \
        "selp.b32 %0, 1, 0, p;\n\t}"                                               \
        : "=r"(_done) : "r"(_m), "r"(_p) : "memory");                              \
    if (!_done) {                                                                  \
        asm volatile("{\n\t.reg .pred P1;\n\t"                                     \
            "WL_%=:\n\t"                                                           \
            "mbarrier.try_wait.parity.acquire.cta.shared::cta.b64 P1, [%0], %1, 0x989680;\n\t" \
            "@P1 bra.uni WD_%=;\n\t"                                               \
            "bra.uni WL_%=;\n\t"                                                   \
            "WD_%=:\n\t}" :: "r"(_m), "r"(_p) : "memory");                         \
    }                                                                              \
} while (0)
#define TMA_LOAD_3D(smem_addr, tmap, cx, cy, cz, mbar) \
    asm volatile("cp.async.bulk.tensor.3d.shared::cta.global.tile.mbarrier::complete_tx::bytes " \
        "[%0], [%1, {%2, %3, %4}], [%5];" \
        :: "r"((uint32_t)(smem_addr)), "l"(tmap), "r"((int32_t)(cx)), "r"((int32_t)(cy)), \
           "r"((int32_t)(cz)), "r"((uint32_t)(mbar)) : "memory")

// ---------------- legacy grid barrier (end-of-kernel only) ----------------
__device__ __forceinline__ void gridbar(unsigned s) {
    __syncthreads();
    if (threadIdx.x == 0) {
        __threadfence();
        unsigned prev = atomicAdd(&g_cnt, 1u);
        if (prev == RNCTA - 1) {
            atomicExch(&g_cnt, 0u);
            __threadfence();
            atomicExch(&g_sense, s);
        } else {
            while (*((volatile unsigned int*)&g_sense) != s) { }
        }
        __threadfence();
    }
    __syncthreads();
}

// ---------------- prep kernels ----------------
__global__ void transpose_x_kernel(const float* __restrict__ x) {
    __shared__ float tile[32][33];
    int b = blockIdx.z, t0 = blockIdx.x * 32, f0 = blockIdx.y * 32;
    const float* xb = x + (size_t)b * Ff * Tt;
    for (int i = threadIdx.y; i < 32; i += 8)
        tile[i][threadIdx.x] = xb[(size_t)(f0 + i) * Tt + t0 + threadIdx.x];
    __syncthreads();
    for (int i = threadIdx.y; i < 32; i += 8)
        g_xT[((size_t)(t0 + i) * Bb + b) * Ff + f0 + threadIdx.x] = tile[threadIdx.x][i];
}

__global__ void whsplit_kernel(const float* __restrict__ Wh) {
    __shared__ float tile[32][33];
    int k0 = blockIdx.x * 32, h0 = blockIdx.y * 32;
    for (int i = threadIdx.y; i < 32; i += 8)
        tile[i][threadIdx.x] = Wh[(size_t)(k0 + i) * Hh + h0 + threadIdx.x];
    __syncthreads();
    for (int i = threadIdx.y; i < 32; i += 8) {
        float w = tile[threadIdx.x][i];
        __nv_bfloat16 hi = __float2bfloat16(w);
        size_t idx = (size_t)(h0 + i) * Hh + k0 + threadIdx.x;
        g_WhiT[idx] = hi;
        g_WloT[idx] = __float2bfloat16(w - __bfloat162float(hi));
    }
}

// U[t][h][b] = bias[h] + sum_f xT[t][b][f] * Wx[f][h]   (f32x2 SIMT GEMM)
__global__ __launch_bounds__(256) void u_gemm_kernel(const float* __restrict__ Wx,
                                                     const float* __restrict__ bias) {
    const int t  = blockIdx.y;
    const int h0 = blockIdx.x * 64;
    __shared__ __align__(16) float As[16][68];
    __shared__ __align__(16) float Bs[16][68];
    const int tid = threadIdx.x;
    const int tx = tid & 15, ty = tid >> 4;
    const int ar = tid >> 4, ac = (tid & 15) * 4;
    const int bbr = tid >> 2, bf = (tid & 3) * 4;
    const float* Xr = g_xT + ((size_t)t * Bb + bbr) * Ff;

    ull acc[4][2];
    #pragma unroll
    for (int i = 0; i < 4; ++i) { acc[i][0] = 0ull; acc[i][1] = 0ull; }
    float4 ra = *(const float4*)(Wx + (size_t)ar * Hh + h0 + ac);
    float4 rb = *(const float4*)(Xr + bf);

    for (int k0 = 0; k0 < Ff; k0 += 16) {
        *(float4*)&As[ar][ac] = ra;
        Bs[bf + 0][bbr] = rb.x; Bs[bf + 1][bbr] = rb.y;
        Bs[bf + 2][bbr] = rb.z; Bs[bf + 3][bbr] = rb.w;
        __syncthreads();
        if (k0 + 16 < Ff) {
            ra = *(const float4*)(Wx + (size_t)(k0 + 16 + ar) * Hh + h0 + ac);
            rb = *(const float4*)(Xr + k0 + 16 + bf);
        }
        #pragma unroll
        for (int kk = 0; kk < 16; ++kk) {
            float4 a = *(const float4*)&As[kk][4 * ty];
            ulonglong2 b2 = *(const ulonglong2*)&Bs[kk][4 * tx];
            float av[4] = {a.x, a.y, a.z, a.w};
            #pragma unroll
            for (int i = 0; i < 4; ++i) {
                ull sp = pk2(av[i], av[i]);
                acc[i][0] = ffma2(sp, b2.x, acc[i][0]);
                acc[i][1] = ffma2(sp, b2.y, acc[i][1]);
            }
        }
        __syncthreads();
    }
    #pragma unroll
    for (int i = 0; i < 4; ++i) {
        float bv = bias[h0 + 4 * ty + i];
        float2 lo = upk2(acc[i][0]), hi = upk2(acc[i][1]);
        float4 v = make_float4(lo.x + bv, lo.y + bv, hi.x + bv, hi.y + bv);
        *(float4*)&g_U[((size_t)t * Hh + h0 + 4 * ty + i) * Bb + 4 * tx] = v;
    }
}

// ---------------- persistent mma.sync recurrence (b-split, 2-half TMA overlap) ----------------
__global__ __launch_bounds__(512, 1) void rnn_mma_kernel(
    const __grid_constant__ CUtensorMap map_hi,
    const __grid_constant__ CUtensorMap map_lo)
{
    extern __shared__ __align__(1024) char smem[];
    const uint32_t sb = smem_u32(smem);
    const int tid   = threadIdx.x;
    const int w     = tid >> 5;
    const int lane  = tid & 31;
    const int bid   = blockIdx.x;
    const int bhalf = bid >> 6;               // 0 or 1: which 32 batch rows
    const int n0    = (bid & 63) * NCOL;      // hidden-column block
    const int tile  = w & 3;                  // 4 output tiles (2 m x 2 n)
    const int khalf = w >> 2;                 // 0..3: k-quarter of this warp
    const int m0    = (tile & 1) * 16;        // local m base (0..31)
    const int nw    = (tile >> 1) * 8;

    if (tid == 0) { MBARRIER_INIT(sb + MB_BASE, 1); MBARRIER_INIT(sb + MB_BASE + 8, 1); }

    // stage Wh^T hi/lo slice (rows n0..n0+15)
    for (int q = tid; q < 16 * 128; q += 512) {
        int r = q >> 7, u = q & 127;
        *(float4*)(smem + OFF_WHI + r * WSTR + u * 16) =
            ((const float4*)g_WhiT)[(size_t)(n0 + r) * 128 + u];
        *(float4*)(smem + OFF_WLO + r * WSTR + u * 16) =
            ((const float4*)g_WloT)[(size_t)(n0 + r) * 128 + u];
    }

    // t = 0: state = tanh(U[0]) for this CTA's (b-half, n-block): 16h x 32b
    {
        int h = tid >> 5, bl = tid & 31;              // 512 threads = 16x32
        int bg = bhalf * 32 + bl;
        size_t ui = (size_t)(n0 + h) * Bb + bg;
        float v = ftanh(g_U[ui]);
        g_U[ui] = v;
        __nv_bfloat16 hi = __float2bfloat16(v);
        g_Sh[0][(size_t)bg * Hh + n0 + h] = hi;
        g_Sl[0][(size_t)bg * Hh + n0 + h] = __float2bfloat16(v - __bfloat162float(hi));
    }
    asm volatile("fence.proxy.async;" ::: "memory");
    __threadfence();
    __syncthreads();
    if (tid == 0) atomicExch(&g_flag[bid], 1u);       // release: S_0 slice visible

    // per-lane fragment geometry (local b rows 0..31)
    const uint32_t rowA  = (uint32_t)(m0 + (lane & 7) + ((lane >> 3) & 1) * 8);
    const uint32_t laneK = (uint32_t)((lane >> 4) * 16);          // bytes (0/16)
    const uint32_t laneX = (rowA & 7u) << 4;                      // SW128 xor term
    const uint32_t rowOff = rowA * 128u;                          // row base in 4KB box
    const uint32_t wBhi  = sb + OFF_WHI + (uint32_t)(nw + (lane & 7)) * WSTR
                         + (uint32_t)((lane >> 3) * 16);
    const uint32_t wBlo  = wBhi + (OFF_WLO - OFF_WHI);
    const int r0 = m0 + (lane >> 2);                  // local b row
    const int cA = n0 + nw + 2 * (lane & 3);          // global h col

    for (int t = 1; t < Tt; ++t) {
        const int zread  = (t - 1) & 1;
        const int zwrite = t & 1;

        // flat flag barrier over OWN b-half only (64 independent producers)
        if (tid < 64) {
            while (*((volatile unsigned int*)&g_flag[bhalf * 64 + tid]) < (unsigned)t) { }
            __threadfence();
        }
        __syncthreads();

        // two-half TMA: half 0 (k 0..511) from tid0, half 1 (k 512..1023) from tid32
        if (tid == 0) {
            MBARRIER_EXPECT_TX(sb + MB_BASE, HALF_TX);
            #pragma unroll
            for (int s = 0; s < 8; ++s) {
                TMA_LOAD_3D(sb + OFF_S + s * 4096, &map_hi,
                            s * 64, bhalf * 32, zread, sb + MB_BASE);
                TMA_LOAD_3D(sb + OFF_S + S_MAT_BYTES + s * 4096, &map_lo,
                            s * 64, bhalf * 32, zread, sb + MB_BASE);
            }
        } else if (tid == 32) {
            MBARRIER_EXPECT_TX(sb + MB_BASE + 8, HALF_TX);
            #pragma unroll
            for (int s = 8; s < 16; ++s) {
                TMA_LOAD_3D(sb + OFF_S + s * 4096, &map_hi,
                            s * 64, bhalf * 32, zread, sb + MB_BASE + 8);
                TMA_LOAD_3D(sb + OFF_S + S_MAT_BYTES + s * 4096, &map_lo,
                            s * 64, bhalf * 32, zread, sb + MB_BASE + 8);
            }
        }

        // prefetch U[t] for epilogue lanes (khalf==0 warps) while TMA flies
        float u00, u01, u10, u11;
        if (khalf == 0) {
            int bg = bhalf * 32 + r0;
            u00 = g_U[((size_t)t * Hh + cA) * Bb + bg];
            u01 = g_U[((size_t)t * Hh + cA + 1) * Bb + bg];
            u10 = g_U[((size_t)t * Hh + cA) * Bb + bg + 8];
            u11 = g_U[((size_t)t * Hh + cA + 1) * Bb + bg + 8];
        }

        float ahh[4] = {0.f, 0.f, 0.f, 0.f};
        float ahl[4] = {0.f, 0.f, 0.f, 0.f};
        float alh[4] = {0.f, 0.f, 0.f, 0.f};

        // half 0: k strips kp = khalf + 4*kq, kq 0..3 (k < 512)
        MBARRIER_WAIT_PARITY(sb + MB_BASE, (unsigned)((t - 1) & 1));
        #pragma unroll
        for (int kq = 0; kq < 4; ++kq) {
            int kp = khalf + 4 * kq;
            uint32_t bh[4], bl[4];
            uint32_t wk = (uint32_t)(kp * 64);
            ldsm4(bh, wBhi + wk);
            ldsm4(bl, wBlo + wk);
            #pragma unroll
            for (int s = 0; s < 2; ++s) {
                uint32_t kb = (uint32_t)(kp * 64 + s * 32) + laneK;
                uint32_t aoff = (kb >> 7) * 4096u + rowOff + ((kb & 127u) ^ laneX);
                uint32_t ahi[4], alo[4];
                ldsm4(ahi, sb + OFF_S + aoff);
                ldsm4(alo, sb + OFF_S + S_MAT_BYTES + aoff);
                mma16816(ahh, ahi, bh[2 * s], bh[2 * s + 1]);
                mma16816(ahl, ahi, bl[2 * s], bl[2 * s + 1]);
                mma16816(alh, alo, bh[2 * s], bh[2 * s + 1]);
            }
        }
        // half 1: kq 4..7 (k >= 512), overlapped with half-0 compute
        MBARRIER_WAIT_PARITY(sb + MB_BASE + 8, (unsigned)((t - 1) & 1));
        #pragma unroll
        for (int kq = 4; kq < 8; ++kq) {
            int kp = khalf + 4 * kq;
            uint32_t bh[4], bl[4];
            uint32_t wk = (uint32_t)(kp * 64);
            ldsm4(bh, wBhi + wk);
            ldsm4(bl, wBlo + wk);
            #pragma unroll
            for (int s = 0; s < 2; ++s) {
                uint32_t kb = (uint32_t)(kp * 64 + s * 32) + laneK;
                uint32_t aoff = (kb >> 7) * 4096u + rowOff + ((kb & 127u) ^ laneX);
                uint32_t ahi[4], alo[4];
                ldsm4(ahi, sb + OFF_S + aoff);
                ldsm4(alo, sb + OFF_S + S_MAT_BYTES + aoff);
                mma16816(ahh, ahi, bh[2 * s], bh[2 * s + 1]);
                mma16816(ahl, ahi, bl[2 * s], bl[2 * s + 1]);
                mma16816(alh, alo, bh[2 * s], bh[2 * s + 1]);
            }
        }

        float acc[4];
        #pragma unroll
        for (int i = 0; i < 4; ++i) acc[i] = ahh[i] + ahl[i] + alh[i];

        // k-reduction: khalf 1..3 publish, khalf 0 combines
        if (khalf != 0) {
            *(float4*)(smem + OFF_RED +
                (uint32_t)(((khalf - 1) * 4 + tile) * 32 + lane) * 16) =
                make_float4(acc[0], acc[1], acc[2], acc[3]);
        }
        __syncthreads();

        if (khalf == 0) {
            #pragma unroll
            for (int kh = 0; kh < 3; ++kh) {
                float4 p = *(const float4*)(smem + OFF_RED +
                    (uint32_t)((kh * 4 + tile) * 32 + lane) * 16);
                acc[0] += p.x; acc[1] += p.y; acc[2] += p.z; acc[3] += p.w;
            }
            int bg = bhalf * 32 + r0;
            float s00 = ftanh(u00 + acc[0]);
            float s01 = ftanh(u01 + acc[1]);
            float s10 = ftanh(u10 + acc[2]);
            float s11 = ftanh(u11 + acc[3]);
            g_U[((size_t)t * Hh + cA) * Bb + bg]         = s00;
            g_U[((size_t)t * Hh + cA + 1) * Bb + bg]     = s01;
            g_U[((size_t)t * Hh + cA) * Bb + bg + 8]     = s10;
            g_U[((size_t)t * Hh + cA + 1) * Bb + bg + 8] = s11;
            {
                __nv_bfloat16 h0 = __float2bfloat16(s00), h1 = __float2bfloat16(s01);
                __nv_bfloat162 hp; hp.x = h0; hp.y = h1;
                __nv_bfloat162 lp;
                lp.x = __float2bfloat16(s00 - __bfloat162float(h0));
                lp.y = __float2bfloat16(s01 - __bfloat162float(h1));
                *(__nv_bfloat162*)&g_Sh[zwrite][(size_t)bg * Hh + cA] = hp;
                *(__nv_bfloat162*)&g_Sl[zwrite][(size_t)bg * Hh + cA] = lp;
            }
            {
                __nv_bfloat16 h0 = __float2bfloat16(s10), h1 = __float2bfloat16(s11);
                __nv_bfloat162 hp; hp.x = h0; hp.y = h1;
                __nv_bfloat162 lp;
                lp.x = __float2bfloat16(s10 - __bfloat162float(h0));
                lp.y = __float2bfloat16(s11 - __bfloat162float(h1));
                *(__nv_bfloat162*)&g_Sh[zwrite][(size_t)(bg + 8) * Hh + cA] = hp;
                *(__nv_bfloat162*)&g_Sl[zwrite][(size_t)(bg + 8) * Hh + cA] = lp;
            }
        }
        // release S_t slice
        asm volatile("fence.proxy.async;" ::: "memory");
        __threadfence();
        __syncthreads();
        if (tid == 0) atomicExch(&g_flag[bid], (unsigned)(t + 1));
    }

    // drain + deterministic flag reset (graph-replay safe)
    gridbar(1u);
    if (bid == 0 && tid < RNCTA) g_flag[tid] = 0u;
    gridbar(0u);
}

// ---------------- output projection (f32x2 SIMT) ----------------
__global__ __launch_bounds__(256) void out_gemm_kernel(const float* __restrict__ Wout,
                                                       const float* __restrict__ bout,
                                                       float* __restrict__ out) {
    const int t  = blockIdx.y;
    const int o0 = blockIdx.x * 64;
    __shared__ __align__(16) float As[16][68];
    __shared__ __align__(16) float Bs[16][68];
    const int tid = threadIdx.x;
    const int tx = tid & 15, ty = tid >> 4;
    const int r = tid >> 4, c = (tid & 15) * 4;

    ull acc[4][2];
    #pragma unroll
    for (int i = 0; i < 4; ++i) { acc[i][0] = 0ull; acc[i][1] = 0ull; }
    float4 ra = *(const float4*)&g_U[((size_t)t * Hh + r) * Bb + c];
    float4 rb = *(const float4*)(Wout + (size_t)r * Oo + o0 + c);

    for (int k0 = 0; k0 < Hh; k0 += 16) {
        *(float4*)&As[r][c] = ra;
        *(float4*)&Bs[r][c] = rb;
        __syncthreads();
        if (k0 + 16 < Hh) {
            ra = *(const float4*)&g_U[((size_t)t * Hh + k0 + 16 + r) * Bb + c];
            rb = *(const float4*)(Wout + (size_t)(k0 + 16 + r) * Oo + o0 + c);
        }
        #pragma unroll
        for (int kk = 0; kk < 16; ++kk) {
            float4 a = *(const float4*)&As[kk][4 * ty];
            ulonglong2 b2 = *(const ulonglong2*)&Bs[kk][4 * tx];
            float av[4] = {a.x, a.y, a.z, a.w};
            #pragma unroll
            for (int i = 0; i < 4; ++i) {
                ull sp = pk2(av[i], av[i]);
                acc[i][0] = ffma2(sp, b2.x, acc[i][0]);
                acc[i][1] = ffma2(sp, b2.y, acc[i][1]);
            }
        }
        __syncthreads();
    }
    float4 bo = *(const float4*)(bout + o0 + 4 * tx);
    #pragma unroll
    for (int i = 0; i < 4; ++i) {
        float2 lo = upk2(acc[i][0]), hi = upk2(acc[i][1]);
        float4 v = make_float4(lo.x + bo.x, lo.y + bo.y, hi.x + bo.z, hi.y + bo.w);
        int b = 4 * ty + i;
        *(float4*)&out[((size_t)b * Tt + t) * Oo + o0 + 4 * tx] = v;
    }
}

// ---------------- host ----------------
typedef CUresult (*EncodeFn)(CUtensorMap*, CUtensorMapDataType, cuuint32_t, void*,
    const cuuint64_t*, const cuuint64_t*, const cuuint32_t*, const cuuint32_t*,
    CUtensorMapInterleave, CUtensorMapSwizzle, CUtensorMapL2promotion, CUtensorMapFloatOOBfill);

extern "C" void kernel_launch(void* const* d_in, const int* in_sizes, int n_in,
                              void* d_out, int out_size) {
    const float* x    = (const float*)d_in[0];
    const float* Wx   = (const float*)d_in[1];
    const float* Wh   = (const float*)d_in[2];
    const float* bias = (const float*)d_in[3];
    const float* Wout = (const float*)d_in[4];
    const float* bout = (const float*)d_in[5];
    float* out = (float*)d_out;

    cudaFuncSetAttribute(rnn_mma_kernel, cudaFuncAttributeMaxDynamicSharedMemorySize, SMEM_TOTAL);

    void *p_shi = nullptr, *p_slo = nullptr;
    cudaGetSymbolAddress(&p_shi, g_Sh);
    cudaGetSymbolAddress(&p_slo, g_Sl);

    EncodeFn enc = nullptr;
    cudaDriverEntryPointQueryResult qr;
    cudaGetDriverEntryPoint("cuTensorMapEncodeTiled", (void**)&enc, cudaEnableDefault, &qr);

    CUtensorMap map_hi, map_lo;
    cuuint64_t dims[3]    = {Hh, Bb, 2};                      // k, b, buffer
    cuuint64_t strides[2] = {Hh * 2, (cuuint64_t)Bb * Hh * 2};
    cuuint32_t box[3]     = {64, 32, 1};                      // 64 k (128B) x 32 b rows
    cuuint32_t es[3]      = {1, 1, 1};
    enc(&map_hi, CU_TENSOR_MAP_DATA_TYPE_BFLOAT16, 3, p_shi, dims, strides, box, es,
        CU_TENSOR_MAP_INTERLEAVE_NONE, CU_TENSOR_MAP_SWIZZLE_128B,
        CU_TENSOR_MAP_L2_PROMOTION_L2_128B, CU_TENSOR_MAP_FLOAT_OOB_FILL_NONE);
    enc(&map_lo, CU_TENSOR_MAP_DATA_TYPE_BFLOAT16, 3, p_slo, dims, strides, box, es,
        CU_TENSOR_MAP_INTERLEAVE_NONE, CU_TENSOR_MAP_SWIZZLE_128B,
        CU_TENSOR_MAP_L2_PROMOTION_L2_128B, CU_TENSOR_MAP_FLOAT_OOB_FILL_NONE);

    transpose_x_kernel<<<dim3(Tt / 32, Ff / 32, Bb), dim3(32, 8)>>>(x);
    whsplit_kernel    <<<dim3(Hh / 32, Hh / 32),     dim3(32, 8)>>>(Wh);
    u_gemm_kernel     <<<dim3(Hh / 64, Tt), 256>>>(Wx, bias);
    rnn_mma_kernel    <<<RNCTA, 512, SMEM_TOTAL>>>(map_hi, map_lo);
    out_gemm_kernel   <<<dim3(Oo / 64, Tt), 256>>>(Wout, bout, out);
}

// round 16
// speedup vs baseline: 1.1410x; 1.1410x over previous
#include <cuda_runtime.h>
#include <cuda.h>
#include <cuda_bf16.h>
#include <math.h>
#include <cstdint>

#define Bb 64
#define Ff 256
#define Tt 1024
#define Hh 1024
#define Oo 512
#define RNCTA 128         // 2 b-halves x 64 n-blocks (co-resident single wave)
#define NCOL 16           // hidden columns per recurrence CTA
#define WSTR 2064         // Wh smem row stride bytes (2048 + 16 pad)

// SMEM layout (rnn kernel)
#define OFF_WHI 0
#define OFF_WLO 33024                     // 16 * WSTR
#define MB_BASE 66048                     // 2 mbarriers @ +0, +8
#define OFF_S   66560                     // 1024-aligned; hi 64KB + lo 64KB
#define S_MAT_BYTES 65536                 // 32 b-rows x 1024 k x 2B per matrix
#define HALF_TX 65536                     // per-half tx bytes (hi 32KB + lo 32KB)
#define OFF_RED (OFF_S + 2 * S_MAT_BYTES) // 197632
#define SMEM_TOTAL (OFF_RED + 12 * 32 * 16)   // +6KB reduction = 203776

// SMEM layout (out_gemm_tc)
#define CKC 128                           // k per chunk
#define RS  272                           // row stride bytes (256 + 16 pad)
#define OG_TILE 17408                     // 64 rows * RS
#define OG_BUF  (4 * OG_TILE)             // Ahi, Alo, Bhi, Blo = 69632
#define OG_SMEM (2 * OG_BUF)              // double buffer = 139264

typedef unsigned long long ull;

// ---------------- device globals (no allocation allowed) ----------------
__device__ float g_xT[(size_t)Tt * Bb * Ff];          // x as (T,B,F)
__device__ float g_U [(size_t)Tt * Hh * Bb];          // U (pre-activation), [t][h][b]
__device__ __nv_bfloat16 g_WhiT[(size_t)Hh * Hh];     // Wh^T hi  [h][k]
__device__ __nv_bfloat16 g_WloT[(size_t)Hh * Hh];     // Wh^T lo  [h][k]
__device__ __nv_bfloat16 g_SThi[(size_t)Tt * Bb * Hh];// states hi, [t][b][k]
__device__ __nv_bfloat16 g_STlo[(size_t)Tt * Bb * Hh];// states lo
__device__ __nv_bfloat16 g_WoThi[(size_t)Oo * Hh];    // Wout^T hi [o][h]
__device__ __nv_bfloat16 g_WoTlo[(size_t)Oo * Hh];    // Wout^T lo
__device__ unsigned int g_cnt;                        // legacy grid barrier (end only)
__device__ unsigned int g_sense;
__device__ unsigned int g_flag[RNCTA];                // per-CTA step-completion flags

// ---------------- helpers ----------------
__device__ __forceinline__ uint32_t smem_u32(const void* p) {
    uint32_t a;
    asm("{ .reg .u64 t; cvta.to.shared.u64 t, %1; cvt.u32.u64 %0, t; }" : "=r"(a) : "l"(p));
    return a;
}
__device__ __forceinline__ float ftanh(float x) {
    float xc = fminf(fmaxf(x, -15.0f), 15.0f);
    float e  = __expf(2.0f * xc);
    return __fdividef(e - 1.0f, e + 1.0f);
}
__device__ __forceinline__ ull pk2(float lo, float hi) {
    ull r; asm("mov.b64 %0, {%1, %2};" : "=l"(r) : "f"(lo), "f"(hi)); return r;
}
__device__ __forceinline__ ull ffma2(ull a, ull b, ull c) {
    ull d; asm("fma.rn.f32x2 %0, %1, %2, %3;" : "=l"(d) : "l"(a), "l"(b), "l"(c)); return d;
}
__device__ __forceinline__ float2 upk2(ull v) {
    float2 f; asm("mov.b64 {%0, %1}, %2;" : "=f"(f.x), "=f"(f.y) : "l"(v)); return f;
}

// mma.sync m16n8k16 bf16 -> fp32 (base ISA on compute_103)
__device__ __forceinline__ void mma16816(float* d, const uint32_t* a, uint32_t b0, uint32_t b1) {
    asm volatile("mma.sync.aligned.m16n8k16.row.col.f32.bf16.bf16.f32 "
        "{%0,%1,%2,%3}, {%4,%5,%6,%7}, {%8,%9}, {%0,%1,%2,%3};"
        : "+f"(d[0]), "+f"(d[1]), "+f"(d[2]), "+f"(d[3])
        : "r"(a[0]), "r"(a[1]), "r"(a[2]), "r"(a[3]), "r"(b0), "r"(b1));
}
__device__ __forceinline__ void ldsm4(uint32_t* r, uint32_t addr) {
    asm volatile("ldmatrix.sync.aligned.m8n8.x4.shared.b16 {%0,%1,%2,%3}, [%4];"
        : "=r"(r[0]), "=r"(r[1]), "=r"(r[2]), "=r"(r[3]) : "r"(addr));
}
__device__ __forceinline__ void cpasync16(uint32_t dst, const void* src) {
    asm volatile("cp.async.cg.shared.global [%0], [%1], 16;" :: "r"(dst), "l"(src));
}
#define CP_COMMIT() asm volatile("cp.async.commit_group;" ::: "memory")
#define CP_WAIT(n)  asm volatile("cp.async.wait_group %0;" :: "n"(n) : "memory")

// ---------------- TMA / mbarrier (base-ISA) ----------------
#define MBARRIER_INIT(mbar, count) \
    asm volatile("mbarrier.init.shared.b64 [%0], %1;" \
        :: "r"((uint32_t)(mbar)), "r"((uint32_t)(count)) : "memory")
#define MBARRIER_EXPECT_TX(mbar, tx) \
    asm volatile("mbarrier.arrive.expect_tx.shared.b64 _, [%0], %1;" \
        :: "r"((uint32_t)(mbar)), "r"((uint32_t)(tx)) : "memory")
#define MBARRIER_WAIT_PARITY(mbar, parity) do {                                    \
    uint32_t _m = (uint32_t)(mbar), _p = (uint32_t)(parity), _done;                \
    asm volatile("{\n\t.reg .pred p;\n\t"                                          \
        "mbarrier.try_wait.parity.acquire.cta.shared::cta.b64 p, [%1], %2;\n\t"    \
        "selp.b32 %0, 1, 0, p;\n\t}"                                               \
        : "=r"(_done) : "r"(_m), "r"(_p) : "memory");                              \
    if (!_done) {                                                                  \
        asm volatile("{\n\t.reg .pred P1;\n\t"                                     \
            "WL_%=:\n\t"                                                           \
            "mbarrier.try_wait.parity.acquire.cta.shared::cta.b64 P1, [%0], %1, 0x989680;\n\t" \
            "@P1 bra.uni WD_%=;\n\t"                                               \
            "bra.uni WL_%=;\n\t"                                                   \
            "WD_%=:\n\t}" :: "r"(_m), "r"(_p) : "memory");                         \
    }                                                                              \
} while (0)
#define TMA_LOAD_3D(smem_addr, tmap, cx, cy, cz, mbar) \
    asm volatile("cp.async.bulk.tensor.3d.shared::cta.global.tile.mbarrier::complete_tx::bytes " \
        "[%0], [%1, {%2, %3, %4}], [%5];" \
        :: "r"((uint32_t)(smem_addr)), "l"(tmap), "r"((int32_t)(cx)), "r"((int32_t)(cy)), \
           "r"((int32_t)(cz)), "r"((uint32_t)(mbar)) : "memory")

// ---------------- legacy grid barrier (end-of-kernel only) ----------------
__device__ __forceinline__ void gridbar(unsigned s) {
    __syncthreads();
    if (threadIdx.x == 0) {
        __threadfence();
        unsigned prev = atomicAdd(&g_cnt, 1u);
        if (prev == RNCTA - 1) {
            atomicExch(&g_cnt, 0u);
            __threadfence();
            atomicExch(&g_sense, s);
        } else {
            while (*((volatile unsigned int*)&g_sense) != s) { }
        }
        __threadfence();
    }
    __syncthreads();
}

// ---------------- prep kernels ----------------
__global__ void transpose_x_kernel(const float* __restrict__ x) {
    __shared__ float tile[32][33];
    int b = blockIdx.z, t0 = blockIdx.x * 32, f0 = blockIdx.y * 32;
    const float* xb = x + (size_t)b * Ff * Tt;
    for (int i = threadIdx.y; i < 32; i += 8)
        tile[i][threadIdx.x] = xb[(size_t)(f0 + i) * Tt + t0 + threadIdx.x];
    __syncthreads();
    for (int i = threadIdx.y; i < 32; i += 8)
        g_xT[((size_t)(t0 + i) * Bb + b) * Ff + f0 + threadIdx.x] = tile[threadIdx.x][i];
}

__global__ void whsplit_kernel(const float* __restrict__ Wh) {
    __shared__ float tile[32][33];
    int k0 = blockIdx.x * 32, h0 = blockIdx.y * 32;
    for (int i = threadIdx.y; i < 32; i += 8)
        tile[i][threadIdx.x] = Wh[(size_t)(k0 + i) * Hh + h0 + threadIdx.x];
    __syncthreads();
    for (int i = threadIdx.y; i < 32; i += 8) {
        float w = tile[threadIdx.x][i];
        __nv_bfloat16 hi = __float2bfloat16(w);
        size_t idx = (size_t)(h0 + i) * Hh + k0 + threadIdx.x;
        g_WhiT[idx] = hi;
        g_WloT[idx] = __float2bfloat16(w - __bfloat162float(hi));
    }
}

// Wout [h][o] fp32 -> WoutT hi/lo bf16 [o][h]
__global__ void wosplit_kernel(const float* __restrict__ Wout) {
    __shared__ float tile[32][33];
    int k0 = blockIdx.x * 32, o0 = blockIdx.y * 32;       // k = h
    for (int i = threadIdx.y; i < 32; i += 8)
        tile[i][threadIdx.x] = Wout[(size_t)(k0 + i) * Oo + o0 + threadIdx.x];
    __syncthreads();
    for (int i = threadIdx.y; i < 32; i += 8) {
        float w = tile[threadIdx.x][i];                   // Wout[k0+tx][o0+i]
        __nv_bfloat16 hi = __float2bfloat16(w);
        size_t idx = (size_t)(o0 + i) * Hh + k0 + threadIdx.x;
        g_WoThi[idx] = hi;
        g_WoTlo[idx] = __float2bfloat16(w - __bfloat162float(hi));
    }
}

// U[t][h][b] = bias[h] + sum_f xT[t][b][f] * Wx[f][h]   (f32x2 SIMT GEMM)
__global__ __launch_bounds__(256) void u_gemm_kernel(const float* __restrict__ Wx,
                                                     const float* __restrict__ bias) {
    const int t  = blockIdx.y;
    const int h0 = blockIdx.x * 64;
    __shared__ __align__(16) float As[16][68];
    __shared__ __align__(16) float Bs[16][68];
    const int tid = threadIdx.x;
    const int tx = tid & 15, ty = tid >> 4;
    const int ar = tid >> 4, ac = (tid & 15) * 4;
    const int bbr = tid >> 2, bf = (tid & 3) * 4;
    const float* Xr = g_xT + ((size_t)t * Bb + bbr) * Ff;

    ull acc[4][2];
    #pragma unroll
    for (int i = 0; i < 4; ++i) { acc[i][0] = 0ull; acc[i][1] = 0ull; }
    float4 ra = *(const float4*)(Wx + (size_t)ar * Hh + h0 + ac);
    float4 rb = *(const float4*)(Xr + bf);

    for (int k0 = 0; k0 < Ff; k0 += 16) {
        *(float4*)&As[ar][ac] = ra;
        Bs[bf + 0][bbr] = rb.x; Bs[bf + 1][bbr] = rb.y;
        Bs[bf + 2][bbr] = rb.z; Bs[bf + 3][bbr] = rb.w;
        __syncthreads();
        if (k0 + 16 < Ff) {
            ra = *(const float4*)(Wx + (size_t)(k0 + 16 + ar) * Hh + h0 + ac);
            rb = *(const float4*)(Xr + k0 + 16 + bf);
        }
        #pragma unroll
        for (int kk = 0; kk < 16; ++kk) {
            float4 a = *(const float4*)&As[kk][4 * ty];
            ulonglong2 b2 = *(const ulonglong2*)&Bs[kk][4 * tx];
            float av[4] = {a.x, a.y, a.z, a.w};
            #pragma unroll
            for (int i = 0; i < 4; ++i) {
                ull sp = pk2(av[i], av[i]);
                acc[i][0] = ffma2(sp, b2.x, acc[i][0]);
                acc[i][1] = ffma2(sp, b2.y, acc[i][1]);
            }
        }
        __syncthreads();
    }
    #pragma unroll
    for (int i = 0; i < 4; ++i) {
        float bv = bias[h0 + 4 * ty + i];
        float2 lo = upk2(acc[i][0]), hi = upk2(acc[i][1]);
        float4 v = make_float4(lo.x + bv, lo.y + bv, hi.x + bv, hi.y + bv);
        *(float4*)&g_U[((size_t)t * Hh + h0 + 4 * ty + i) * Bb + 4 * tx] = v;
    }
}

// ---------------- persistent mma.sync recurrence (per-t state arrays) ----------------
__global__ __launch_bounds__(512, 1) void rnn_mma_kernel(
    const __grid_constant__ CUtensorMap map_hi,
    const __grid_constant__ CUtensorMap map_lo)
{
    extern __shared__ __align__(1024) char smem[];
    const uint32_t sb = smem_u32(smem);
    const int tid   = threadIdx.x;
    const int w     = tid >> 5;
    const int lane  = tid & 31;
    const int bid   = blockIdx.x;
    const int bhalf = bid >> 6;               // 0 or 1: which 32 batch rows
    const int n0    = (bid & 63) * NCOL;      // hidden-column block
    const int tile  = w & 3;                  // 4 output tiles (2 m x 2 n)
    const int khalf = w >> 2;                 // 0..3: k-quarter of this warp
    const int m0    = (tile & 1) * 16;        // local m base (0..31)
    const int nw    = (tile >> 1) * 8;

    if (tid == 0) { MBARRIER_INIT(sb + MB_BASE, 1); MBARRIER_INIT(sb + MB_BASE + 8, 1); }

    // stage Wh^T hi/lo slice (rows n0..n0+15)
    for (int q = tid; q < 16 * 128; q += 512) {
        int r = q >> 7, u = q & 127;
        *(float4*)(smem + OFF_WHI + r * WSTR + u * 16) =
            ((const float4*)g_WhiT)[(size_t)(n0 + r) * 128 + u];
        *(float4*)(smem + OFF_WLO + r * WSTR + u * 16) =
            ((const float4*)g_WloT)[(size_t)(n0 + r) * 128 + u];
    }

    // t = 0: state = tanh(U[0]) for this CTA's (b-half, n-block): 16h x 32b
    {
        int h = tid >> 5, bl = tid & 31;              // 512 threads = 16x32
        int bg = bhalf * 32 + bl;
        float v = ftanh(g_U[(size_t)(n0 + h) * Bb + bg]);
        __nv_bfloat16 hi = __float2bfloat16(v);
        g_SThi[(size_t)bg * Hh + n0 + h] = hi;        // t=0 slice
        g_STlo[(size_t)bg * Hh + n0 + h] = __float2bfloat16(v - __bfloat162float(hi));
    }
    asm volatile("fence.proxy.async;" ::: "memory");
    __threadfence();
    __syncthreads();
    if (tid == 0) atomicExch(&g_flag[bid], 1u);       // release: slice 0 visible

    // per-lane fragment geometry (local b rows 0..31)
    const uint32_t rowA  = (uint32_t)(m0 + (lane & 7) + ((lane >> 3) & 1) * 8);
    const uint32_t laneK = (uint32_t)((lane >> 4) * 16);          // bytes (0/16)
    const uint32_t laneX = (rowA & 7u) << 4;                      // SW128 xor term
    const uint32_t rowOff = rowA * 128u;                          // row base in 4KB box
    const uint32_t wBhi  = sb + OFF_WHI + (uint32_t)(nw + (lane & 7)) * WSTR
                         + (uint32_t)((lane >> 3) * 16);
    const uint32_t wBlo  = wBhi + (OFF_WLO - OFF_WHI);
    const int r0 = m0 + (lane >> 2);                  // local b row
    const int cA = n0 + nw + 2 * (lane & 3);          // global h col

    for (int t = 1; t < Tt; ++t) {
        // flat flag barrier over OWN b-half only (64 independent producers)
        if (tid < 64) {
            while (*((volatile unsigned int*)&g_flag[bhalf * 64 + tid]) < (unsigned)t) { }
            __threadfence();
        }
        __syncthreads();

        // two-half TMA of slice t-1: half 0 (k<512) tid0, half 1 tid32
        if (tid == 0) {
            MBARRIER_EXPECT_TX(sb + MB_BASE, HALF_TX);
            #pragma unroll
            for (int s = 0; s < 8; ++s) {
                TMA_LOAD_3D(sb + OFF_S + s * 4096, &map_hi,
                            s * 64, bhalf * 32, t - 1, sb + MB_BASE);
                TMA_LOAD_3D(sb + OFF_S + S_MAT_BYTES + s * 4096, &map_lo,
                            s * 64, bhalf * 32, t - 1, sb + MB_BASE);
            }
        } else if (tid == 32) {
            MBARRIER_EXPECT_TX(sb + MB_BASE + 8, HALF_TX);
            #pragma unroll
            for (int s = 8; s < 16; ++s) {
                TMA_LOAD_3D(sb + OFF_S + s * 4096, &map_hi,
                            s * 64, bhalf * 32, t - 1, sb + MB_BASE + 8);
                TMA_LOAD_3D(sb + OFF_S + S_MAT_BYTES + s * 4096, &map_lo,
                            s * 64, bhalf * 32, t - 1, sb + MB_BASE + 8);
            }
        }

        // prefetch U[t] for epilogue lanes (khalf==0 warps) while TMA flies
        float u00, u01, u10, u11;
        if (khalf == 0) {
            int bg = bhalf * 32 + r0;
            u00 = g_U[((size_t)t * Hh + cA) * Bb + bg];
            u01 = g_U[((size_t)t * Hh + cA + 1) * Bb + bg];
            u10 = g_U[((size_t)t * Hh + cA) * Bb + bg + 8];
            u11 = g_U[((size_t)t * Hh + cA + 1) * Bb + bg + 8];
        }

        float ahh[4] = {0.f, 0.f, 0.f, 0.f};
        float ahl[4] = {0.f, 0.f, 0.f, 0.f};
        float alh[4] = {0.f, 0.f, 0.f, 0.f};

        MBARRIER_WAIT_PARITY(sb + MB_BASE, (unsigned)((t - 1) & 1));
        #pragma unroll
        for (int kq = 0; kq < 4; ++kq) {
            int kp = khalf + 4 * kq;
            uint32_t bh[4], bl[4];
            uint32_t wk = (uint32_t)(kp * 64);
            ldsm4(bh, wBhi + wk);
            ldsm4(bl, wBlo + wk);
            #pragma unroll
            for (int s = 0; s < 2; ++s) {
                uint32_t kb = (uint32_t)(kp * 64 + s * 32) + laneK;
                uint32_t aoff = (kb >> 7) * 4096u + rowOff + ((kb & 127u) ^ laneX);
                uint32_t ahi[4], alo[4];
                ldsm4(ahi, sb + OFF_S + aoff);
                ldsm4(alo, sb + OFF_S + S_MAT_BYTES + aoff);
                mma16816(ahh, ahi, bh[2 * s], bh[2 * s + 1]);
                mma16816(ahl, ahi, bl[2 * s], bl[2 * s + 1]);
                mma16816(alh, alo, bh[2 * s], bh[2 * s + 1]);
            }
        }
        MBARRIER_WAIT_PARITY(sb + MB_BASE + 8, (unsigned)((t - 1) & 1));
        #pragma unroll
        for (int kq = 4; kq < 8; ++kq) {
            int kp = khalf + 4 * kq;
            uint32_t bh[4], bl[4];
            uint32_t wk = (uint32_t)(kp * 64);
            ldsm4(bh, wBhi + wk);
            ldsm4(bl, wBlo + wk);
            #pragma unroll
            for (int s = 0; s < 2; ++s) {
                uint32_t kb = (uint32_t)(kp * 64 + s * 32) + laneK;
                uint32_t aoff = (kb >> 7) * 4096u + rowOff + ((kb & 127u) ^ laneX);
                uint32_t ahi[4], alo[4];
                ldsm4(ahi, sb + OFF_S + aoff);
                ldsm4(alo, sb + OFF_S + S_MAT_BYTES + aoff);
                mma16816(ahh, ahi, bh[2 * s], bh[2 * s + 1]);
                mma16816(ahl, ahi, bl[2 * s], bl[2 * s + 1]);
                mma16816(alh, alo, bh[2 * s], bh[2 * s + 1]);
            }
        }

        float acc[4];
        #pragma unroll
        for (int i = 0; i < 4; ++i) acc[i] = ahh[i] + ahl[i] + alh[i];

        if (khalf != 0) {
            *(float4*)(smem + OFF_RED +
                (uint32_t)(((khalf - 1) * 4 + tile) * 32 + lane) * 16) =
                make_float4(acc[0], acc[1], acc[2], acc[3]);
        }
        __syncthreads();

        if (khalf == 0) {
            #pragma unroll
            for (int kh = 0; kh < 3; ++kh) {
                float4 p = *(const float4*)(smem + OFF_RED +
                    (uint32_t)((kh * 4 + tile) * 32 + lane) * 16);
                acc[0] += p.x; acc[1] += p.y; acc[2] += p.z; acc[3] += p.w;
            }
            int bg = bhalf * 32 + r0;
            float s00 = ftanh(u00 + acc[0]);
            float s01 = ftanh(u01 + acc[1]);
            float s10 = ftanh(u10 + acc[2]);
            float s11 = ftanh(u11 + acc[3]);
            size_t base0 = ((size_t)t * Bb + bg) * Hh + cA;
            size_t base1 = ((size_t)t * Bb + bg + 8) * Hh + cA;
            {
                __nv_bfloat16 h0 = __float2bfloat16(s00), h1 = __float2bfloat16(s01);
                __nv_bfloat162 hp; hp.x = h0; hp.y = h1;
                __nv_bfloat162 lp;
                lp.x = __float2bfloat16(s00 - __bfloat162float(h0));
                lp.y = __float2bfloat16(s01 - __bfloat162float(h1));
                *(__nv_bfloat162*)&g_SThi[base0] = hp;
                *(__nv_bfloat162*)&g_STlo[base0] = lp;
            }
            {
                __nv_bfloat16 h0 = __float2bfloat16(s10), h1 = __float2bfloat16(s11);
                __nv_bfloat162 hp; hp.x = h0; hp.y = h1;
                __nv_bfloat162 lp;
                lp.x = __float2bfloat16(s10 - __bfloat162float(h0));
                lp.y = __float2bfloat16(s11 - __bfloat162float(h1));
                *(__nv_bfloat162*)&g_SThi[base1] = hp;
                *(__nv_bfloat162*)&g_STlo[base1] = lp;
            }
        }
        asm volatile("fence.proxy.async;" ::: "memory");
        __threadfence();
        __syncthreads();
        if (tid == 0) atomicExch(&g_flag[bid], (unsigned)(t + 1));
    }

    // drain + deterministic flag reset (graph-replay safe)
    gridbar(1u);
    if (bid == 0 && tid < RNCTA) g_flag[tid] = 0u;
    gridbar(0u);
}

// ---------------- output projection (bf16 double-split mma.sync) ----------------
__device__ __forceinline__ void og_load_chunk(uint32_t sb, int buf, int t, int o0,
                                              int c, int tid) {
    const int k0 = c * CKC;
    #pragma unroll
    for (int i = 0; i < 16; ++i) {
        int seg = tid + i * 256;                   // 0..4095
        int mat = seg >> 10;                       // 0 Ahi, 1 Alo, 2 Bhi, 3 Blo
        int within = seg & 1023;
        int row = within >> 4, u = within & 15;
        const __nv_bfloat16* src;
        if      (mat == 0) src = &g_SThi[((size_t)t * Bb + row) * Hh + k0 + u * 8];
        else if (mat == 1) src = &g_STlo[((size_t)t * Bb + row) * Hh + k0 + u * 8];
        else if (mat == 2) src = &g_WoThi[(size_t)(o0 + row) * Hh + k0 + u * 8];
        else               src = &g_WoTlo[(size_t)(o0 + row) * Hh + k0 + u * 8];
        cpasync16(sb + (uint32_t)(buf * OG_BUF + mat * OG_TILE + row * RS + u * 16), src);
    }
    CP_COMMIT();
}

__global__ __launch_bounds__(256, 1) void out_tc_kernel(const float* __restrict__ bout,
                                                        float* __restrict__ out) {
    extern __shared__ __align__(1024) char smem[];
    const uint32_t sb = smem_u32(smem);
    const int tid  = threadIdx.x;
    const int w    = tid >> 5;
    const int lane = tid & 31;
    const int t  = blockIdx.y;
    const int o0 = blockIdx.x * 64;
    const int m0w = (w & 3) * 16;                 // b-tile
    const int n0w = (w >> 2) * 32;                // o-tile (32 wide)

    // fragment geometry
    const uint32_t rowA  = (uint32_t)(m0w + (lane & 7) + ((lane >> 3) & 1) * 8);
    const uint32_t laneK = (uint32_t)((lane >> 4) * 16);
    const uint32_t aRel  = rowA * RS + laneK;      // + buf*OG_BUF (+OG_TILE for lo)
    uint32_t bRel[4];
    #pragma unroll
    for (int j = 0; j < 4; ++j)
        bRel[j] = (uint32_t)(2 * OG_TILE + (n0w + j * 8 + (lane & 7)) * RS
                             + (lane >> 3) * 16);

    float hh[4][4], hl[4][4], lh[4][4];
    #pragma unroll
    for (int j = 0; j < 4; ++j)
        #pragma unroll
        for (int i = 0; i < 4; ++i) { hh[j][i] = 0.f; hl[j][i] = 0.f; lh[j][i] = 0.f; }

    og_load_chunk(sb, 0, t, o0, 0, tid);

    for (int c = 0; c < Hh / CKC; ++c) {
        if (c + 1 < Hh / CKC) {
            og_load_chunk(sb, (c + 1) & 1, t, o0, c + 1, tid);
            CP_WAIT(1);
        } else {
            CP_WAIT(0);
        }
        __syncthreads();
        const uint32_t bb = sb + (uint32_t)((c & 1) * OG_BUF);
        #pragma unroll
        for (int kb = 0; kb < 4; ++kb) {           // k32 blocks
            uint32_t bh[4][4], bl[4][4];
            #pragma unroll
            for (int j = 0; j < 4; ++j) {
                ldsm4(bh[j], bb + bRel[j] + kb * 64);
                ldsm4(bl[j], bb + bRel[j] + OG_TILE + kb * 64);
            }
            #pragma unroll
            for (int s = 0; s < 2; ++s) {
                uint32_t ahi[4], alo[4];
                uint32_t ka = (uint32_t)(kb * 64 + s * 32);
                ldsm4(ahi, bb + aRel + ka);
                ldsm4(alo, bb + aRel + OG_TILE + ka);
                #pragma unroll
                for (int j = 0; j < 4; ++j) {
                    mma16816(hh[j], ahi, bh[j][2 * s], bh[j][2 * s + 1]);
                    mma16816(hl[j], ahi, bl[j][2 * s], bl[j][2 * s + 1]);
                    mma16816(lh[j], alo, bh[j][2 * s], bh[j][2 * s + 1]);
                }
            }
        }
        __syncthreads();
    }

    // epilogue: out[b][t][o] = acc + bout[o]
    const int r0 = m0w + (lane >> 2);
    #pragma unroll
    for (int j = 0; j < 4; ++j) {
        int c0 = n0w + j * 8 + 2 * (lane & 3);
        float b0 = bout[o0 + c0], b1 = bout[o0 + c0 + 1];
        float v0 = hh[j][0] + hl[j][0] + lh[j][0] + b0;
        float v1 = hh[j][1] + hl[j][1] + lh[j][1] + b1;
        float v2 = hh[j][2] + hl[j][2] + lh[j][2] + b0;
        float v3 = hh[j][3] + hl[j][3] + lh[j][3] + b1;
        *(float2*)&out[((size_t)r0 * Tt + t) * Oo + o0 + c0]       = make_float2(v0, v1);
        *(float2*)&out[((size_t)(r0 + 8) * Tt + t) * Oo + o0 + c0] = make_float2(v2, v3);
    }
}

// ---------------- host ----------------
typedef CUresult (*EncodeFn)(CUtensorMap*, CUtensorMapDataType, cuuint32_t, void*,
    const cuuint64_t*, const cuuint64_t*, const cuuint32_t*, const cuuint32_t*,
    CUtensorMapInterleave, CUtensorMapSwizzle, CUtensorMapL2promotion, CUtensorMapFloatOOBfill);

extern "C" void kernel_launch(void* const* d_in, const int* in_sizes, int n_in,
                              void* d_out, int out_size) {
    const float* x    = (const float*)d_in[0];
    const float* Wx   = (const float*)d_in[1];
    const float* Wh   = (const float*)d_in[2];
    const float* bias = (const float*)d_in[3];
    const float* Wout = (const float*)d_in[4];
    const float* bout = (const float*)d_in[5];
    float* out = (float*)d_out;

    cudaFuncSetAttribute(rnn_mma_kernel, cudaFuncAttributeMaxDynamicSharedMemorySize, SMEM_TOTAL);
    cudaFuncSetAttribute(out_tc_kernel, cudaFuncAttributeMaxDynamicSharedMemorySize, OG_SMEM);

    void *p_shi = nullptr, *p_slo = nullptr;
    cudaGetSymbolAddress(&p_shi, g_SThi);
    cudaGetSymbolAddress(&p_slo, g_STlo);

    EncodeFn enc = nullptr;
    cudaDriverEntryPointQueryResult qr;
    cudaGetDriverEntryPoint("cuTensorMapEncodeTiled", (void**)&enc, cudaEnableDefault, &qr);

    CUtensorMap map_hi, map_lo;
    cuuint64_t dims[3]    = {Hh, Bb, Tt};                     // k, b, t
    cuuint64_t strides[2] = {Hh * 2, (cuuint64_t)Bb * Hh * 2};
    cuuint32_t box[3]     = {64, 32, 1};                      // 64 k (128B) x 32 b rows
    cuuint32_t es[3]      = {1, 1, 1};
    enc(&map_hi, CU_TENSOR_MAP_DATA_TYPE_BFLOAT16, 3, p_shi, dims, strides, box, es,
        CU_TENSOR_MAP_INTERLEAVE_NONE, CU_TENSOR_MAP_SWIZZLE_128B,
        CU_TENSOR_MAP_L2_PROMOTION_L2_128B, CU_TENSOR_MAP_FLOAT_OOB_FILL_NONE);
    enc(&map_lo, CU_TENSOR_MAP_DATA_TYPE_BFLOAT16, 3, p_slo, dims, strides, box, es,
        CU_TENSOR_MAP_INTERLEAVE_NONE, CU_TENSOR_MAP_SWIZZLE_128B,
        CU_TENSOR_MAP_L2_PROMOTION_L2_128B, CU_TENSOR_MAP_FLOAT_OOB_FILL_NONE);

    transpose_x_kernel<<<dim3(Tt / 32, Ff / 32, Bb), dim3(32, 8)>>>(x);
    whsplit_kernel    <<<dim3(Hh / 32, Hh / 32),     dim3(32, 8)>>>(Wh);
    wosplit_kernel    <<<dim3(Hh / 32, Oo / 32),     dim3(32, 8)>>>(Wout);
    u_gemm_kernel     <<<dim3(Hh / 64, Tt), 256>>>(Wx, bias);
    rnn_mma_kernel    <<<RNCTA, 512, SMEM_TOTAL>>>(map_hi, map_lo);
    out_tc_kernel     <<<dim3(Oo / 64, Tt), 256, OG_SMEM>>>(bout, out);
}